// round 1
// baseline (speedup 1.0000x reference)
#include <cuda_runtime.h>
#include <math.h>
#include <stdint.h>
#include <stddef.h>

#define DHID 768
#define NB   64
#define NLP  1024
#define NLQ  128

// Scratch (allocation-free rule: __device__ globals)
__device__ float g_Wp[(size_t)NB * NLP * DHID];   // 192 MiB
__device__ float g_Wq[(size_t)NB * NLQ * DHID];   // 24 MiB
__device__ float g_qbias[NB * NLQ];

// ---------------------------------------------------------------------------
// Mask prep: q_mask is a bool array; its on-disk dtype could be u8, int32, or
// float32 depending on harness canonicalization. Detect from byte pattern:
//  - int32 {0,1}: all bytes at i%4!=0 are zero
//  - float32 {0.0,1.0}: byte at i%4==3 equals 0x3F for ones
//  - u8 {0,1}: nonzero bytes at misaligned positions, never 0x3F at i%4==3
// Converts to additive bias: masked -> -1e30, valid -> 0.
// ---------------------------------------------------------------------------
__global__ void mask_prep_kernel(const unsigned char* __restrict__ qm, int n) {
    __shared__ int mode;  // 0=int32, 1=u8, 2=float32
    if (threadIdx.x == 0) mode = 0;
    __syncthreads();
    for (int i = threadIdx.x; i < n; i += blockDim.x) {
        int r = i & 3;
        unsigned char c = qm[i];
        if (r != 0 && c != 0) {
            if (r == 3 && c == 0x3F) atomicMax(&mode, 2);
            else                     atomicMax(&mode, 1);
        }
    }
    __syncthreads();
    int m = mode;
    for (int i = threadIdx.x; i < n; i += blockDim.x) {
        int v;
        if (m == 2)      v = (((const float*)(const void*)qm)[i] != 0.0f);
        else if (m == 1) v = (qm[i] != 0);
        else             v = (((const int*)(const void*)qm)[i] != 0);
        g_qbias[i] = v ? -1e30f : 0.0f;
    }
}

// ---------------------------------------------------------------------------
// C[M,768] = relu(A[M,768] @ W[768,768] + b)
// Block tile 128x128, K-chunk 16, 256 threads, 8x8 microtile per thread.
// ---------------------------------------------------------------------------
__global__ __launch_bounds__(256)
void gemm_relu_kernel(const float* __restrict__ A, const float* __restrict__ W,
                      const float* __restrict__ bias, float* __restrict__ C) {
    __shared__ float As[16][132];  // transposed A tile: As[k][m]
    __shared__ float Bs[16][132];  // Bs[k][n]

    const int tid = threadIdx.x;
    const int tx = tid & 15;       // n microtile index
    const int ty = tid >> 4;       // m microtile index
    const int rowBase = blockIdx.y * 128;
    const int colBase = blockIdx.x * 128;

    float acc[8][8];
#pragma unroll
    for (int i = 0; i < 8; ++i)
#pragma unroll
        for (int j = 0; j < 8; ++j) acc[i][j] = 0.0f;

    for (int kt = 0; kt < DHID; kt += 16) {
        // A tile: 128 rows x 16 cols, store transposed
#pragma unroll
        for (int l = 0; l < 2; ++l) {
            int f = tid + l * 256;           // 0..511 float4 slots
            int r  = f >> 2;                 // row 0..127
            int c4 = (f & 3) << 2;           // col 0,4,8,12
            float4 v = *(const float4*)(A + (size_t)(rowBase + r) * DHID + kt + c4);
            As[c4 + 0][r] = v.x; As[c4 + 1][r] = v.y;
            As[c4 + 2][r] = v.z; As[c4 + 3][r] = v.w;
        }
        // W tile: 16 rows x 128 cols, direct
#pragma unroll
        for (int l = 0; l < 2; ++l) {
            int f = tid + l * 256;
            int r  = f >> 5;                 // 0..15
            int c4 = (f & 31) << 2;          // 0..124
            *(float4*)&Bs[r][c4] =
                *(const float4*)(W + (size_t)(kt + r) * DHID + colBase + c4);
        }
        __syncthreads();
#pragma unroll
        for (int k = 0; k < 16; ++k) {
            float4 a0 = *(float4*)&As[k][ty * 8];
            float4 a1 = *(float4*)&As[k][ty * 8 + 4];
            float4 b0 = *(float4*)&Bs[k][tx * 8];
            float4 b1 = *(float4*)&Bs[k][tx * 8 + 4];
            float a[8] = {a0.x, a0.y, a0.z, a0.w, a1.x, a1.y, a1.z, a1.w};
            float b[8] = {b0.x, b0.y, b0.z, b0.w, b1.x, b1.y, b1.z, b1.w};
#pragma unroll
            for (int i = 0; i < 8; ++i)
#pragma unroll
                for (int j = 0; j < 8; ++j) acc[i][j] = fmaf(a[i], b[j], acc[i][j]);
        }
        __syncthreads();
    }

    float bb[8];
#pragma unroll
    for (int j = 0; j < 8; ++j) bb[j] = bias[colBase + tx * 8 + j];
#pragma unroll
    for (int i = 0; i < 8; ++i) {
        float4 r0, r1;
        r0.x = fmaxf(acc[i][0] + bb[0], 0.0f);
        r0.y = fmaxf(acc[i][1] + bb[1], 0.0f);
        r0.z = fmaxf(acc[i][2] + bb[2], 0.0f);
        r0.w = fmaxf(acc[i][3] + bb[3], 0.0f);
        r1.x = fmaxf(acc[i][4] + bb[4], 0.0f);
        r1.y = fmaxf(acc[i][5] + bb[5], 0.0f);
        r1.z = fmaxf(acc[i][6] + bb[6], 0.0f);
        r1.w = fmaxf(acc[i][7] + bb[7], 0.0f);
        float* cp = C + (size_t)(rowBase + ty * 8 + i) * DHID + colBase + tx * 8;
        *(float4*)cp       = r0;
        *(float4*)(cp + 4) = r1;
    }
}

// ---------------------------------------------------------------------------
// Fused attention block: one block = (batch b, 128-row p-tile)
//  phase 1: scores[128p][128q] = Wp_tile @ Wq_b^T  (+ mask bias)
//  phase 2: row softmax in smem, write alpha transposed
//  phase 3: out_tile[128p][768] = alpha @ question_b
// ---------------------------------------------------------------------------
#define SC_PITCH  133
#define SCT_PITCH 132
#define TILE_PITCH 132

__global__ __launch_bounds__(256)
void attn_kernel(const float* __restrict__ question, float* __restrict__ out) {
    extern __shared__ float sm[];
    float* sc  = sm;                                  // [128][133] scores
    float* scT = sc  + 128 * SC_PITCH;                // [128][132] alpha^T [q][p]
    float* As  = scT + 128 * SCT_PITCH;               // [16][132] (phase1 WpT / phase3 Q tile)
    float* Bs  = As  + 16 * TILE_PITCH;               // [16][132] (phase1 WqT)
    float* qb  = Bs  + 16 * TILE_PITCH;               // [128]

    const int tid = threadIdx.x;
    const int tx = tid & 15;
    const int ty = tid >> 4;
    const int b = blockIdx.y;
    const int pBase = blockIdx.x * 128;

    if (tid < 128) qb[tid] = g_qbias[b * NLQ + tid];

    const float* Ap = g_Wp + ((size_t)b * NLP + pBase) * DHID;
    const float* Bq = g_Wq + (size_t)b * NLQ * DHID;

    // ---------------- phase 1: scores ----------------
    float acc[8][8];
#pragma unroll
    for (int i = 0; i < 8; ++i)
#pragma unroll
        for (int j = 0; j < 8; ++j) acc[i][j] = 0.0f;

    for (int kt = 0; kt < DHID; kt += 16) {
#pragma unroll
        for (int l = 0; l < 2; ++l) {     // Wp tile -> As[k][p]
            int f = tid + l * 256;
            int r  = f >> 2;
            int c4 = (f & 3) << 2;
            float4 v = *(const float4*)(Ap + (size_t)r * DHID + kt + c4);
            As[(c4 + 0) * TILE_PITCH + r] = v.x;
            As[(c4 + 1) * TILE_PITCH + r] = v.y;
            As[(c4 + 2) * TILE_PITCH + r] = v.z;
            As[(c4 + 3) * TILE_PITCH + r] = v.w;
        }
#pragma unroll
        for (int l = 0; l < 2; ++l) {     // Wq tile -> Bs[k][q]
            int f = tid + l * 256;
            int r  = f >> 2;              // q row
            int c4 = (f & 3) << 2;
            float4 v = *(const float4*)(Bq + (size_t)r * DHID + kt + c4);
            Bs[(c4 + 0) * TILE_PITCH + r] = v.x;
            Bs[(c4 + 1) * TILE_PITCH + r] = v.y;
            Bs[(c4 + 2) * TILE_PITCH + r] = v.z;
            Bs[(c4 + 3) * TILE_PITCH + r] = v.w;
        }
        __syncthreads();
#pragma unroll
        for (int k = 0; k < 16; ++k) {
            float4 a0 = *(float4*)&As[k * TILE_PITCH + ty * 8];
            float4 a1 = *(float4*)&As[k * TILE_PITCH + ty * 8 + 4];
            float4 b0 = *(float4*)&Bs[k * TILE_PITCH + tx * 8];
            float4 b1 = *(float4*)&Bs[k * TILE_PITCH + tx * 8 + 4];
            float a[8] = {a0.x, a0.y, a0.z, a0.w, a1.x, a1.y, a1.z, a1.w};
            float bv[8] = {b0.x, b0.y, b0.z, b0.w, b1.x, b1.y, b1.z, b1.w};
#pragma unroll
            for (int i = 0; i < 8; ++i)
#pragma unroll
                for (int j = 0; j < 8; ++j) acc[i][j] = fmaf(a[i], bv[j], acc[i][j]);
        }
        __syncthreads();
    }

    // mask + store scores
#pragma unroll
    for (int i = 0; i < 8; ++i)
#pragma unroll
        for (int j = 0; j < 8; ++j)
            sc[(ty * 8 + i) * SC_PITCH + tx * 8 + j] = acc[i][j] + qb[tx * 8 + j];
    __syncthreads();

    // ---------------- phase 2: softmax ----------------
    if (tid < 128) {
        float* row = sc + tid * SC_PITCH;
        float mx = -INFINITY;
#pragma unroll 8
        for (int c = 0; c < 128; ++c) mx = fmaxf(mx, row[c]);
        float s = 0.0f;
#pragma unroll 8
        for (int c = 0; c < 128; ++c) {
            float e = __expf(row[c] - mx);
            row[c] = e;
            s += e;
        }
        float inv = 1.0f / s;
#pragma unroll 8
        for (int c = 0; c < 128; ++c) scT[c * SCT_PITCH + tid] = row[c] * inv;
    }
    __syncthreads();

    // ---------------- phase 3: out = alpha @ question ----------------
    const float* Qb = question + (size_t)b * NLQ * DHID;
    for (int nc = 0; nc < DHID; nc += 128) {
        float o[8][8];
#pragma unroll
        for (int i = 0; i < 8; ++i)
#pragma unroll
            for (int j = 0; j < 8; ++j) o[i][j] = 0.0f;

        for (int kt = 0; kt < 128; kt += 16) {
            // question tile -> As[k][n] (reuse As as Qs)
#pragma unroll
            for (int l = 0; l < 2; ++l) {
                int f = tid + l * 256;
                int r  = f >> 5;               // k row 0..15
                int c4 = (f & 31) << 2;        // n col
                *(float4*)&As[r * TILE_PITCH + c4] =
                    *(const float4*)(Qb + (size_t)(kt + r) * DHID + nc + c4);
            }
            __syncthreads();
#pragma unroll
            for (int k = 0; k < 16; ++k) {
                float4 a0 = *(float4*)&scT[(kt + k) * SCT_PITCH + ty * 8];
                float4 a1 = *(float4*)&scT[(kt + k) * SCT_PITCH + ty * 8 + 4];
                float4 b0 = *(float4*)&As[k * TILE_PITCH + tx * 8];
                float4 b1 = *(float4*)&As[k * TILE_PITCH + tx * 8 + 4];
                float a[8] = {a0.x, a0.y, a0.z, a0.w, a1.x, a1.y, a1.z, a1.w};
                float bv[8] = {b0.x, b0.y, b0.z, b0.w, b1.x, b1.y, b1.z, b1.w};
#pragma unroll
                for (int i = 0; i < 8; ++i)
#pragma unroll
                    for (int j = 0; j < 8; ++j) o[i][j] = fmaf(a[i], bv[j], o[i][j]);
            }
            __syncthreads();
        }
#pragma unroll
        for (int i = 0; i < 8; ++i) {
            float* op = out + ((size_t)b * NLP + pBase + ty * 8 + i) * DHID + nc + tx * 8;
            float4 r0 = {o[i][0], o[i][1], o[i][2], o[i][3]};
            float4 r1 = {o[i][4], o[i][5], o[i][6], o[i][7]};
            *(float4*)op       = r0;
            *(float4*)(op + 4) = r1;
        }
    }
}

// ---------------------------------------------------------------------------
extern "C" void kernel_launch(void* const* d_in, const int* in_sizes, int n_in,
                              void* d_out, int out_size) {
    const float* passage  = (const float*)d_in[0];
    // d_in[1] = p_mask : unused by the reference
    const float* question = (const float*)d_in[2];
    const unsigned char* qmask = (const unsigned char*)d_in[3];
    const float* Ww = (const float*)d_in[4];
    const float* Wb = (const float*)d_in[5];
    float* out = (float*)d_out;

    float *wp = nullptr, *wq = nullptr;
    cudaGetSymbolAddress((void**)&wp, g_Wp);
    cudaGetSymbolAddress((void**)&wq, g_Wq);

    mask_prep_kernel<<<1, 256>>>(qmask, NB * NLQ);

    // Wq = relu(question @ W + b): M = 64*128 = 8192
    gemm_relu_kernel<<<dim3(DHID / 128, (NB * NLQ) / 128), 256>>>(question, Ww, Wb, wq);
    // Wp = relu(passage @ W + b): M = 64*1024 = 65536
    gemm_relu_kernel<<<dim3(DHID / 128, (NB * NLP) / 128), 256>>>(passage, Ww, Wb, wp);

    const int smem_bytes =
        (128 * SC_PITCH + 128 * SCT_PITCH + 2 * 16 * TILE_PITCH + 128) * (int)sizeof(float);
    cudaFuncSetAttribute(attn_kernel, cudaFuncAttributeMaxDynamicSharedMemorySize, smem_bytes);
    attn_kernel<<<dim3(NLP / 128, NB), 256, smem_bytes>>>(question, out);
}

// round 3
// speedup vs baseline: 1.7185x; 1.7185x over previous
#include <cuda_runtime.h>
#include <cuda_bf16.h>
#include <math.h>
#include <stdint.h>
#include <stddef.h>

#define DHID 768
#define NB   64
#define NLP  1024
#define NLQ  128

// ---------------- scratch (__device__ globals; allocation-free rule) --------
__device__ float g_Wp[(size_t)NB * NLP * DHID];   // relu(passage@W+b) fp32
__device__ float g_Wq[(size_t)NB * NLQ * DHID];   // relu(question@W+b) fp32
__device__ float g_qbias[NB * NLQ];
__device__ __align__(16) __nv_bfloat16 g_Ph[(size_t)NB * NLP * DHID];
__device__ __align__(16) __nv_bfloat16 g_Pl[(size_t)NB * NLP * DHID];
__device__ __align__(16) __nv_bfloat16 g_Qh[(size_t)NB * NLQ * DHID];
__device__ __align__(16) __nv_bfloat16 g_Ql[(size_t)NB * NLQ * DHID];
__device__ __align__(16) __nv_bfloat16 g_Wth[DHID * DHID];   // W^T hi [n][k]
__device__ __align__(16) __nv_bfloat16 g_Wtl[DHID * DHID];   // W^T lo [n][k]

// ---------------- small asm helpers ----------------------------------------
__device__ __forceinline__ uint32_t smem_u32(const void* p) {
    uint32_t a;
    asm("{ .reg .u64 t; cvta.to.shared.u64 t, %1; cvt.u32.u64 %0, t; }" : "=r"(a) : "l"(p));
    return a;
}
__device__ __forceinline__ void cp16(uint32_t dst, const void* src) {
    asm volatile("cp.async.cg.shared.global [%0], [%1], 16;" :: "r"(dst), "l"(src));
}
#define CP_COMMIT() asm volatile("cp.async.commit_group;" ::: "memory")
#define CP_WAIT1()  asm volatile("cp.async.wait_group 1;" ::: "memory")
#define CP_WAIT0()  asm volatile("cp.async.wait_group 0;" ::: "memory")

__device__ __forceinline__ void ldsm4(uint32_t& r0, uint32_t& r1, uint32_t& r2,
                                      uint32_t& r3, uint32_t a) {
    asm volatile("ldmatrix.sync.aligned.m8n8.x4.shared.b16 {%0,%1,%2,%3}, [%4];"
                 : "=r"(r0), "=r"(r1), "=r"(r2), "=r"(r3) : "r"(a));
}
__device__ __forceinline__ void mma16816(float* c, uint32_t a0, uint32_t a1,
                                         uint32_t a2, uint32_t a3,
                                         uint32_t b0, uint32_t b1) {
    asm volatile("mma.sync.aligned.m16n8k16.row.col.f32.bf16.bf16.f32 "
                 "{%0,%1,%2,%3}, {%4,%5,%6,%7}, {%8,%9}, {%0,%1,%2,%3};"
                 : "+f"(c[0]), "+f"(c[1]), "+f"(c[2]), "+f"(c[3])
                 : "r"(a0), "r"(a1), "r"(a2), "r"(a3), "r"(b0), "r"(b1));
}

// ---------------- mask prep (dtype-sniffing) --------------------------------
__global__ void mask_prep_kernel(const unsigned char* __restrict__ qm, int n) {
    __shared__ int mode;
    if (threadIdx.x == 0) mode = 0;
    __syncthreads();
    for (int i = threadIdx.x; i < n; i += blockDim.x) {
        int r = i & 3;
        unsigned char c = qm[i];
        if (r != 0 && c != 0) {
            if (r == 3 && c == 0x3F) atomicMax(&mode, 2);
            else                     atomicMax(&mode, 1);
        }
    }
    __syncthreads();
    int m = mode;
    for (int i = threadIdx.x; i < n; i += blockDim.x) {
        int v;
        if (m == 2)      v = (((const float*)(const void*)qm)[i] != 0.0f);
        else if (m == 1) v = (qm[i] != 0);
        else             v = (((const int*)(const void*)qm)[i] != 0);
        g_qbias[i] = v ? -1e30f : 0.0f;
    }
}

// ---------------- fp32 -> (hi,lo) bf16 split --------------------------------
__global__ void split_kernel(const float4* __restrict__ x,
                             __nv_bfloat162* __restrict__ h,
                             __nv_bfloat162* __restrict__ l, int n4) {
    int i = blockIdx.x * blockDim.x + threadIdx.x;
    if (i >= n4) return;
    float4 v = x[i];
    __nv_bfloat16 h0 = __float2bfloat16(v.x), h1 = __float2bfloat16(v.y);
    __nv_bfloat16 h2 = __float2bfloat16(v.z), h3 = __float2bfloat16(v.w);
    __nv_bfloat16 l0 = __float2bfloat16(v.x - __bfloat162float(h0));
    __nv_bfloat16 l1 = __float2bfloat16(v.y - __bfloat162float(h1));
    __nv_bfloat16 l2 = __float2bfloat16(v.z - __bfloat162float(h2));
    __nv_bfloat16 l3 = __float2bfloat16(v.w - __bfloat162float(h3));
    h[i * 2]     = __nv_bfloat162(h0, h1);
    h[i * 2 + 1] = __nv_bfloat162(h2, h3);
    l[i * 2]     = __nv_bfloat162(l0, l1);
    l[i * 2 + 1] = __nv_bfloat162(l2, l3);
}

// ---------------- W[k][n] -> W^T split (hi/lo) ------------------------------
__global__ void wsplit_kernel(const float* __restrict__ W,
                              __nv_bfloat16* __restrict__ Wth,
                              __nv_bfloat16* __restrict__ Wtl) {
    __shared__ float t[32][33];
    int bx = blockIdx.x * 32;  // k
    int by = blockIdx.y * 32;  // n
    for (int yy = threadIdx.y; yy < 32; yy += 8)
        t[yy][threadIdx.x] = W[(size_t)(bx + yy) * DHID + by + threadIdx.x];
    __syncthreads();
    for (int yy = threadIdx.y; yy < 32; yy += 8) {
        float v = t[threadIdx.x][yy];   // k = bx+tx, n = by+yy
        __nv_bfloat16 h = __float2bfloat16(v);
        size_t o = (size_t)(by + yy) * DHID + bx + threadIdx.x;
        Wth[o] = h;
        Wtl[o] = __float2bfloat16(v - __bfloat162float(h));
    }
}

// ---------------- split-bf16 GEMM via mma.sync (legacy HMMA pipe) -----------
// C[128m x 128n] = relu(A @ W^T_rows + b); 3 products accumulate fp32:
// Ah*Bh + Al*Bh + Ah*Bl.  K chunks of 32, cp.async double buffer.
#define GP_B      80                  // smem row pitch bytes (40 bf16)
#define ARR_B     (128 * GP_B)        // 10240 per array
#define O_AH      0
#define O_AL      (1 * ARR_B)
#define O_BH      (2 * ARR_B)
#define O_BL      (3 * ARR_B)
#define STAGE_B   (4 * ARR_B)         // 40960
#define GSMEM     (2 * STAGE_B + 512)
#define NCHUNK    (DHID / 32)         // 24

__device__ __forceinline__ void load_stage(uint32_t dst, int kc, int tid,
                                           const __nv_bfloat16* __restrict__ A_h,
                                           const __nv_bfloat16* __restrict__ A_l,
                                           const __nv_bfloat16* __restrict__ B_h,
                                           const __nv_bfloat16* __restrict__ B_l) {
#pragma unroll
    for (int i = 0; i < 2; ++i) {
        int idx = tid + i * 256;          // 0..511
        int row = idx >> 2;               // 0..127
        int c   = idx & 3;                // 16B chunk
        uint32_t d = dst + (uint32_t)(row * GP_B + c * 16);
        size_t so = (size_t)row * DHID + kc + c * 8;
        cp16(d + O_AH, A_h + so);
        cp16(d + O_AL, A_l + so);
        cp16(d + O_BH, B_h + so);
        cp16(d + O_BL, B_l + so);
    }
}

__global__ __launch_bounds__(256)
void gemm_mma_kernel(const __nv_bfloat16* __restrict__ Ah,
                     const __nv_bfloat16* __restrict__ Al,
                     const __nv_bfloat16* __restrict__ Bh,
                     const __nv_bfloat16* __restrict__ Bl,
                     const float* __restrict__ bias,
                     float* __restrict__ Cout) {
    extern __shared__ char smem[];
    uint32_t sb = smem_u32(smem);
    float* bias_s = (float*)(smem + 2 * STAGE_B);

    const int tid  = threadIdx.x;
    const int w    = tid >> 5;
    const int lane = tid & 31;
    const int wm   = w >> 2;              // 0..1   (m: 64-row half)
    const int wn   = w & 3;               // 0..3   (n: 32-col strip)
    const size_t mBase = (size_t)blockIdx.y * 128;
    const int    nBase = blockIdx.x * 128;

    if (tid < 128) bias_s[tid] = bias[nBase + tid];

    const __nv_bfloat16* A_h = Ah + mBase * DHID;
    const __nv_bfloat16* A_l = Al + mBase * DHID;
    const __nv_bfloat16* B_h = Bh + (size_t)nBase * DHID;  // W^T rows n
    const __nv_bfloat16* B_l = Bl + (size_t)nBase * DHID;

    // ldmatrix lane address offsets (pitch GP_B, 16B-aligned: GP_B=5*16)
    const int j  = lane >> 3;     // matrix index 0..3
    const int rj = lane & 7;      // row within 8x8
    uint32_t aoff[4], boff[2];
#pragma unroll
    for (int mi = 0; mi < 4; ++mi)   // A matrices: (m0-7,k0-7),(m8-15,k0-7),(m0-7,k8-15),(m8-15,k8-15)
        aoff[mi] = (uint32_t)((wm * 64 + mi * 16 + (j & 1) * 8 + rj) * GP_B + (j >> 1) * 16);
#pragma unroll
    for (int p = 0; p < 2; ++p)      // B matrices: (n0-7,k0-7),(n0-7,k8-15),(n8-15,k0-7),(n8-15,k8-15)
        boff[p] = (uint32_t)((wn * 32 + p * 16 + (j >> 1) * 8 + rj) * GP_B + (j & 1) * 16);

    float acc[4][4][4];
#pragma unroll
    for (int mi = 0; mi < 4; ++mi)
#pragma unroll
        for (int ni = 0; ni < 4; ++ni)
#pragma unroll
            for (int r = 0; r < 4; ++r) acc[mi][ni][r] = 0.0f;

    load_stage(sb, 0, tid, A_h, A_l, B_h, B_l);
    CP_COMMIT();

    for (int t = 0; t < NCHUNK; ++t) {
        uint32_t st = sb + (uint32_t)(t & 1) * STAGE_B;
        if (t + 1 < NCHUNK) {
            load_stage(sb + (uint32_t)((t + 1) & 1) * STAGE_B, (t + 1) * 32, tid,
                       A_h, A_l, B_h, B_l);
            CP_COMMIT();
            CP_WAIT1();
        } else {
            CP_WAIT0();
        }
        __syncthreads();
#pragma unroll
        for (int ks = 0; ks < 2; ++ks) {
            uint32_t k2 = (uint32_t)ks * 32;   // 16 bf16 = 32 bytes
            uint32_t ah[4][4], al[4][4], bh[4][2], bl[4][2];
#pragma unroll
            for (int mi = 0; mi < 4; ++mi)
                ldsm4(ah[mi][0], ah[mi][1], ah[mi][2], ah[mi][3], st + O_AH + aoff[mi] + k2);
#pragma unroll
            for (int mi = 0; mi < 4; ++mi)
                ldsm4(al[mi][0], al[mi][1], al[mi][2], al[mi][3], st + O_AL + aoff[mi] + k2);
#pragma unroll
            for (int p = 0; p < 2; ++p) {
                uint32_t r0, r1, r2, r3;
                ldsm4(r0, r1, r2, r3, st + O_BH + boff[p] + k2);
                bh[p * 2][0] = r0; bh[p * 2][1] = r1;
                bh[p * 2 + 1][0] = r2; bh[p * 2 + 1][1] = r3;
                ldsm4(r0, r1, r2, r3, st + O_BL + boff[p] + k2);
                bl[p * 2][0] = r0; bl[p * 2][1] = r1;
                bl[p * 2 + 1][0] = r2; bl[p * 2 + 1][1] = r3;
            }
#pragma unroll
            for (int mi = 0; mi < 4; ++mi)
#pragma unroll
                for (int ni = 0; ni < 4; ++ni) {
                    mma16816(acc[mi][ni], ah[mi][0], ah[mi][1], ah[mi][2], ah[mi][3],
                             bh[ni][0], bh[ni][1]);
                    mma16816(acc[mi][ni], al[mi][0], al[mi][1], al[mi][2], al[mi][3],
                             bh[ni][0], bh[ni][1]);
                    mma16816(acc[mi][ni], ah[mi][0], ah[mi][1], ah[mi][2], ah[mi][3],
                             bl[ni][0], bl[ni][1]);
                }
        }
        __syncthreads();
    }

    // epilogue: bias + relu, fp32 store
    const int rGrp = lane >> 2;          // 0..7
    const int cGrp = (lane & 3) * 2;     // 0,2,4,6
#pragma unroll
    for (int mi = 0; mi < 4; ++mi) {
        size_t gr = mBase + wm * 64 + mi * 16 + rGrp;
#pragma unroll
        for (int ni = 0; ni < 4; ++ni) {
            int lc = wn * 32 + ni * 8 + cGrp;
            float b0 = bias_s[lc], b1 = bias_s[lc + 1];
            float2 v0 = {fmaxf(acc[mi][ni][0] + b0, 0.0f),
                         fmaxf(acc[mi][ni][1] + b1, 0.0f)};
            float2 v1 = {fmaxf(acc[mi][ni][2] + b0, 0.0f),
                         fmaxf(acc[mi][ni][3] + b1, 0.0f)};
            *(float2*)(Cout + gr * DHID + nBase + lc)       = v0;
            *(float2*)(Cout + (gr + 8) * DHID + nBase + lc) = v1;
        }
    }
}

// ---------------- fused attention (smem-reduced: 2 CTAs/SM) -----------------
#define SC_PITCH   133
#define TILE_PITCH 132

__global__ __launch_bounds__(256, 2)
void attn_kernel(const float* __restrict__ question, float* __restrict__ out) {
    extern __shared__ float sm[];
    float* sc = sm;                               // [128][133] scores/alpha
    float* As = sc + 128 * SC_PITCH;              // [16][132]
    float* Bs = As + 16 * TILE_PITCH;             // [16][132]
    float* qb = Bs + 16 * TILE_PITCH;             // [128]

    const int tid = threadIdx.x;
    const int tx = tid & 15;
    const int ty = tid >> 4;
    const int b = blockIdx.y;
    const int pBase = blockIdx.x * 128;

    if (tid < 128) qb[tid] = g_qbias[b * NLQ + tid];

    const float* Ap = g_Wp + ((size_t)b * NLP + pBase) * DHID;
    const float* Bq = g_Wq + (size_t)b * NLQ * DHID;

    // ---- phase 1: scores = Wp_tile @ Wq^T ----
    float acc[8][8];
#pragma unroll
    for (int i = 0; i < 8; ++i)
#pragma unroll
        for (int j = 0; j < 8; ++j) acc[i][j] = 0.0f;

    for (int kt = 0; kt < DHID; kt += 16) {
#pragma unroll
        for (int l = 0; l < 2; ++l) {
            int f = tid + l * 256;
            int r  = f >> 2;
            int c4 = (f & 3) << 2;
            float4 v = *(const float4*)(Ap + (size_t)r * DHID + kt + c4);
            As[(c4 + 0) * TILE_PITCH + r] = v.x;
            As[(c4 + 1) * TILE_PITCH + r] = v.y;
            As[(c4 + 2) * TILE_PITCH + r] = v.z;
            As[(c4 + 3) * TILE_PITCH + r] = v.w;
        }
#pragma unroll
        for (int l = 0; l < 2; ++l) {
            int f = tid + l * 256;
            int r  = f >> 2;
            int c4 = (f & 3) << 2;
            float4 v = *(const float4*)(Bq + (size_t)r * DHID + kt + c4);
            Bs[(c4 + 0) * TILE_PITCH + r] = v.x;
            Bs[(c4 + 1) * TILE_PITCH + r] = v.y;
            Bs[(c4 + 2) * TILE_PITCH + r] = v.z;
            Bs[(c4 + 3) * TILE_PITCH + r] = v.w;
        }
        __syncthreads();
#pragma unroll
        for (int k = 0; k < 16; ++k) {
            float4 a0 = *(float4*)&As[k * TILE_PITCH + ty * 8];
            float4 a1 = *(float4*)&As[k * TILE_PITCH + ty * 8 + 4];
            float4 b0 = *(float4*)&Bs[k * TILE_PITCH + tx * 8];
            float4 b1 = *(float4*)&Bs[k * TILE_PITCH + tx * 8 + 4];
            float a[8] = {a0.x, a0.y, a0.z, a0.w, a1.x, a1.y, a1.z, a1.w};
            float bv[8] = {b0.x, b0.y, b0.z, b0.w, b1.x, b1.y, b1.z, b1.w};
#pragma unroll
            for (int i = 0; i < 8; ++i)
#pragma unroll
                for (int j = 0; j < 8; ++j) acc[i][j] = fmaf(a[i], bv[j], acc[i][j]);
        }
        __syncthreads();
    }
#pragma unroll
    for (int i = 0; i < 8; ++i)
#pragma unroll
        for (int j = 0; j < 8; ++j)
            sc[(ty * 8 + i) * SC_PITCH + tx * 8 + j] = acc[i][j] + qb[tx * 8 + j];
    __syncthreads();

    // ---- phase 2: in-place softmax per p-row ----
    if (tid < 128) {
        float* row = sc + tid * SC_PITCH;
        float mx = -INFINITY;
#pragma unroll 8
        for (int c = 0; c < 128; ++c) mx = fmaxf(mx, row[c]);
        float s = 0.0f;
#pragma unroll 8
        for (int c = 0; c < 128; ++c) {
            float e = __expf(row[c] - mx);
            row[c] = e;
            s += e;
        }
        float inv = 1.0f / s;
#pragma unroll 8
        for (int c = 0; c < 128; ++c) row[c] *= inv;
    }
    __syncthreads();

    // ---- phase 3: out = alpha @ question ----
    const float* Qb = question + (size_t)b * NLQ * DHID;
    for (int nc = 0; nc < DHID; nc += 128) {
        float o[8][8];
#pragma unroll
        for (int i = 0; i < 8; ++i)
#pragma unroll
            for (int j = 0; j < 8; ++j) o[i][j] = 0.0f;

        for (int kt = 0; kt < 128; kt += 16) {
#pragma unroll
            for (int l = 0; l < 2; ++l) {
                int f = tid + l * 256;
                int r  = f >> 5;
                int c4 = (f & 31) << 2;
                *(float4*)&As[r * TILE_PITCH + c4] =
                    *(const float4*)(Qb + (size_t)(kt + r) * DHID + nc + c4);
            }
            __syncthreads();
#pragma unroll
            for (int k = 0; k < 16; ++k) {
                float a[8];
#pragma unroll
                for (int i = 0; i < 8; ++i)
                    a[i] = sc[(ty * 8 + i) * SC_PITCH + kt + k];   // LDS broadcast
                float4 b0 = *(float4*)&As[k * TILE_PITCH + tx * 8];
                float4 b1 = *(float4*)&As[k * TILE_PITCH + tx * 8 + 4];
                float bv[8] = {b0.x, b0.y, b0.z, b0.w, b1.x, b1.y, b1.z, b1.w};
#pragma unroll
                for (int i = 0; i < 8; ++i)
#pragma unroll
                    for (int j = 0; j < 8; ++j) o[i][j] = fmaf(a[i], bv[j], o[i][j]);
            }
            __syncthreads();
        }
#pragma unroll
        for (int i = 0; i < 8; ++i) {
            float* op = out + ((size_t)b * NLP + pBase + ty * 8 + i) * DHID + nc + tx * 8;
            float4 r0 = {o[i][0], o[i][1], o[i][2], o[i][3]};
            float4 r1 = {o[i][4], o[i][5], o[i][6], o[i][7]};
            *(float4*)op       = r0;
            *(float4*)(op + 4) = r1;
        }
    }
}

// ---------------------------------------------------------------------------
extern "C" void kernel_launch(void* const* d_in, const int* in_sizes, int n_in,
                              void* d_out, int out_size) {
    const float* passage  = (const float*)d_in[0];
    const float* question = (const float*)d_in[2];
    const unsigned char* qmask = (const unsigned char*)d_in[3];
    const float* Ww = (const float*)d_in[4];
    const float* Wb = (const float*)d_in[5];
    float* out = (float*)d_out;

    float *wp, *wq;
    __nv_bfloat16 *ph, *pl, *qh, *ql, *wth, *wtl;
    cudaGetSymbolAddress((void**)&wp,  g_Wp);
    cudaGetSymbolAddress((void**)&wq,  g_Wq);
    cudaGetSymbolAddress((void**)&ph,  g_Ph);
    cudaGetSymbolAddress((void**)&pl,  g_Pl);
    cudaGetSymbolAddress((void**)&qh,  g_Qh);
    cudaGetSymbolAddress((void**)&ql,  g_Ql);
    cudaGetSymbolAddress((void**)&wth, g_Wth);
    cudaGetSymbolAddress((void**)&wtl, g_Wtl);

    mask_prep_kernel<<<1, 256>>>(qmask, NB * NLQ);

    int np4 = NB * NLP * DHID / 4;
    int nq4 = NB * NLQ * DHID / 4;
    split_kernel<<<(np4 + 255) / 256, 256>>>((const float4*)passage,
                                             (__nv_bfloat162*)ph, (__nv_bfloat162*)pl, np4);
    split_kernel<<<(nq4 + 255) / 256, 256>>>((const float4*)question,
                                             (__nv_bfloat162*)qh, (__nv_bfloat162*)ql, nq4);
    wsplit_kernel<<<dim3(DHID / 32, DHID / 32), dim3(32, 8)>>>(Ww, wth, wtl);

    cudaFuncSetAttribute(gemm_mma_kernel, cudaFuncAttributeMaxDynamicSharedMemorySize, GSMEM);
    gemm_mma_kernel<<<dim3(DHID / 128, (NB * NLQ) / 128), 256, GSMEM>>>(qh, ql, wth, wtl, Wb, wq);
    gemm_mma_kernel<<<dim3(DHID / 128, (NB * NLP) / 128), 256, GSMEM>>>(ph, pl, wth, wtl, Wb, wp);

    const int attn_smem = (128 * SC_PITCH + 2 * 16 * TILE_PITCH + 128) * (int)sizeof(float);
    cudaFuncSetAttribute(attn_kernel, cudaFuncAttributeMaxDynamicSharedMemorySize, attn_smem);
    attn_kernel<<<dim3(NLP / 128, NB), 256, attn_smem>>>(question, out);
}

// round 4
// speedup vs baseline: 2.2009x; 1.2807x over previous
#include <cuda_runtime.h>
#include <cuda_bf16.h>
#include <math.h>
#include <stdint.h>
#include <stddef.h>

#define DHID 768
#define NB   64
#define NLP  1024
#define NLQ  128

// ---------------- scratch (__device__ globals; allocation-free rule) --------
__device__ float g_qbias[NB * NLQ];
__device__ __align__(16) __nv_bfloat16 g_Ph[(size_t)NB * NLP * DHID];
__device__ __align__(16) __nv_bfloat16 g_Pl[(size_t)NB * NLP * DHID];
__device__ __align__(16) __nv_bfloat16 g_Qh[(size_t)NB * NLQ * DHID];
__device__ __align__(16) __nv_bfloat16 g_Ql[(size_t)NB * NLQ * DHID];
__device__ __align__(16) __nv_bfloat16 g_Wth[DHID * DHID];   // W^T hi [n][k]
__device__ __align__(16) __nv_bfloat16 g_Wtl[DHID * DHID];   // W^T lo [n][k]
__device__ __align__(16) __nv_bfloat16 g_Wph[(size_t)NB * NLP * DHID];
__device__ __align__(16) __nv_bfloat16 g_Wpl[(size_t)NB * NLP * DHID];
__device__ __align__(16) __nv_bfloat16 g_Wqh[(size_t)NB * NLQ * DHID];
__device__ __align__(16) __nv_bfloat16 g_Wql[(size_t)NB * NLQ * DHID];

// ---------------- small asm helpers ----------------------------------------
__device__ __forceinline__ uint32_t smem_u32(const void* p) {
    uint32_t a;
    asm("{ .reg .u64 t; cvta.to.shared.u64 t, %1; cvt.u32.u64 %0, t; }" : "=r"(a) : "l"(p));
    return a;
}
__device__ __forceinline__ void cp16(uint32_t dst, const void* src) {
    asm volatile("cp.async.cg.shared.global [%0], [%1], 16;" :: "r"(dst), "l"(src));
}
#define CP_COMMIT() asm volatile("cp.async.commit_group;" ::: "memory")
#define CP_WAIT1()  asm volatile("cp.async.wait_group 1;" ::: "memory")
#define CP_WAIT0()  asm volatile("cp.async.wait_group 0;" ::: "memory")

__device__ __forceinline__ void ldsm4(uint32_t& r0, uint32_t& r1, uint32_t& r2,
                                      uint32_t& r3, uint32_t a) {
    asm volatile("ldmatrix.sync.aligned.m8n8.x4.shared.b16 {%0,%1,%2,%3}, [%4];"
                 : "=r"(r0), "=r"(r1), "=r"(r2), "=r"(r3) : "r"(a));
}
__device__ __forceinline__ void ldsm4t(uint32_t& r0, uint32_t& r1, uint32_t& r2,
                                       uint32_t& r3, uint32_t a) {
    asm volatile("ldmatrix.sync.aligned.m8n8.x4.trans.shared.b16 {%0,%1,%2,%3}, [%4];"
                 : "=r"(r0), "=r"(r1), "=r"(r2), "=r"(r3) : "r"(a));
}
__device__ __forceinline__ void mma16816(float* c, uint32_t a0, uint32_t a1,
                                         uint32_t a2, uint32_t a3,
                                         uint32_t b0, uint32_t b1) {
    asm volatile("mma.sync.aligned.m16n8k16.row.col.f32.bf16.bf16.f32 "
                 "{%0,%1,%2,%3}, {%4,%5,%6,%7}, {%8,%9}, {%0,%1,%2,%3};"
                 : "+f"(c[0]), "+f"(c[1]), "+f"(c[2]), "+f"(c[3])
                 : "r"(a0), "r"(a1), "r"(a2), "r"(a3), "r"(b0), "r"(b1));
}
__device__ __forceinline__ void split2(float v, __nv_bfloat16& h, __nv_bfloat16& l) {
    h = __float2bfloat16(v);
    l = __float2bfloat16(v - __bfloat162float(h));
}

// ---------------- mask prep (dtype-sniffing) --------------------------------
__global__ void mask_prep_kernel(const unsigned char* __restrict__ qm, int n) {
    __shared__ int mode;
    if (threadIdx.x == 0) mode = 0;
    __syncthreads();
    for (int i = threadIdx.x; i < n; i += blockDim.x) {
        int r = i & 3;
        unsigned char c = qm[i];
        if (r != 0 && c != 0) {
            if (r == 3 && c == 0x3F) atomicMax(&mode, 2);
            else                     atomicMax(&mode, 1);
        }
    }
    __syncthreads();
    int m = mode;
    for (int i = threadIdx.x; i < n; i += blockDim.x) {
        int v;
        if (m == 2)      v = (((const float*)(const void*)qm)[i] != 0.0f);
        else if (m == 1) v = (qm[i] != 0);
        else             v = (((const int*)(const void*)qm)[i] != 0);
        g_qbias[i] = v ? -1e30f : 0.0f;
    }
}

// ---------------- fp32 -> (hi,lo) bf16 split --------------------------------
__global__ void split_kernel(const float4* __restrict__ x,
                             __nv_bfloat162* __restrict__ h,
                             __nv_bfloat162* __restrict__ l, int n4) {
    int i = blockIdx.x * blockDim.x + threadIdx.x;
    if (i >= n4) return;
    float4 v = x[i];
    __nv_bfloat16 h0, h1, h2, h3, l0, l1, l2, l3;
    split2(v.x, h0, l0); split2(v.y, h1, l1);
    split2(v.z, h2, l2); split2(v.w, h3, l3);
    h[i * 2]     = __nv_bfloat162(h0, h1);
    h[i * 2 + 1] = __nv_bfloat162(h2, h3);
    l[i * 2]     = __nv_bfloat162(l0, l1);
    l[i * 2 + 1] = __nv_bfloat162(l2, l3);
}

// ---------------- W[k][n] -> W^T split (hi/lo) ------------------------------
__global__ void wsplit_kernel(const float* __restrict__ W,
                              __nv_bfloat16* __restrict__ Wth,
                              __nv_bfloat16* __restrict__ Wtl) {
    __shared__ float t[32][33];
    int bx = blockIdx.x * 32;  // k
    int by = blockIdx.y * 32;  // n
    for (int yy = threadIdx.y; yy < 32; yy += 8)
        t[yy][threadIdx.x] = W[(size_t)(bx + yy) * DHID + by + threadIdx.x];
    __syncthreads();
    for (int yy = threadIdx.y; yy < 32; yy += 8) {
        float v = t[threadIdx.x][yy];
        __nv_bfloat16 h, l;
        split2(v, h, l);
        size_t o = (size_t)(by + yy) * DHID + bx + threadIdx.x;
        Wth[o] = h;
        Wtl[o] = l;
    }
}

// ---------------- common tiling constants -----------------------------------
#define GP_B      80                  // smem row pitch bytes (40 bf16)
#define ARR_B     (128 * GP_B)        // 10240 per array
#define O_AH      0
#define O_AL      (1 * ARR_B)
#define O_BH      (2 * ARR_B)
#define O_BL      (3 * ARR_B)
#define STAGE_B   (4 * ARR_B)         // 40960
#define NCHUNK    (DHID / 32)         // 24

__device__ __forceinline__ void load_stage(uint32_t dst, int kc, int tid,
                                           const __nv_bfloat16* __restrict__ A_h,
                                           const __nv_bfloat16* __restrict__ A_l,
                                           const __nv_bfloat16* __restrict__ B_h,
                                           const __nv_bfloat16* __restrict__ B_l) {
#pragma unroll
    for (int i = 0; i < 2; ++i) {
        int idx = tid + i * 256;
        int row = idx >> 2;
        int c   = idx & 3;
        uint32_t d = dst + (uint32_t)(row * GP_B + c * 16);
        size_t so = (size_t)row * DHID + kc + c * 8;
        cp16(d + O_AH, A_h + so);
        cp16(d + O_AL, A_l + so);
        cp16(d + O_BH, B_h + so);
        cp16(d + O_BL, B_l + so);
    }
}

// 3-product split-bf16 mainloop chunk (2 k16 steps), accumulate into acc[4][4][4]
__device__ __forceinline__ void mma_chunk(uint32_t st, const uint32_t* aoff,
                                          const uint32_t* boff, float acc[4][4][4]) {
#pragma unroll
    for (int ks = 0; ks < 2; ++ks) {
        uint32_t k2 = (uint32_t)ks * 32;
        uint32_t ah[4][4], al[4][4], bh[4][2], bl[4][2];
#pragma unroll
        for (int mi = 0; mi < 4; ++mi)
            ldsm4(ah[mi][0], ah[mi][1], ah[mi][2], ah[mi][3], st + O_AH + aoff[mi] + k2);
#pragma unroll
        for (int mi = 0; mi < 4; ++mi)
            ldsm4(al[mi][0], al[mi][1], al[mi][2], al[mi][3], st + O_AL + aoff[mi] + k2);
#pragma unroll
        for (int p = 0; p < 2; ++p) {
            uint32_t r0, r1, r2, r3;
            ldsm4(r0, r1, r2, r3, st + O_BH + boff[p] + k2);
            bh[p * 2][0] = r0; bh[p * 2][1] = r1;
            bh[p * 2 + 1][0] = r2; bh[p * 2 + 1][1] = r3;
            ldsm4(r0, r1, r2, r3, st + O_BL + boff[p] + k2);
            bl[p * 2][0] = r0; bl[p * 2][1] = r1;
            bl[p * 2 + 1][0] = r2; bl[p * 2 + 1][1] = r3;
        }
#pragma unroll
        for (int mi = 0; mi < 4; ++mi)
#pragma unroll
            for (int ni = 0; ni < 4; ++ni) {
                mma16816(acc[mi][ni], ah[mi][0], ah[mi][1], ah[mi][2], ah[mi][3],
                         bh[ni][0], bh[ni][1]);
                mma16816(acc[mi][ni], al[mi][0], al[mi][1], al[mi][2], al[mi][3],
                         bh[ni][0], bh[ni][1]);
                mma16816(acc[mi][ni], ah[mi][0], ah[mi][1], ah[mi][2], ah[mi][3],
                         bl[ni][0], bl[ni][1]);
            }
    }
}

// ---------------- projection GEMM: (hi,lo) = split(relu(A@W^T + b)) ---------
#define GSMEM (2 * STAGE_B + 512)

__global__ __launch_bounds__(256)
void gemm_mma_kernel(const __nv_bfloat16* __restrict__ Ah,
                     const __nv_bfloat16* __restrict__ Al,
                     const __nv_bfloat16* __restrict__ Bh,
                     const __nv_bfloat16* __restrict__ Bl,
                     const float* __restrict__ bias,
                     __nv_bfloat16* __restrict__ Ch,
                     __nv_bfloat16* __restrict__ Cl) {
    extern __shared__ char smem[];
    uint32_t sb = smem_u32(smem);
    float* bias_s = (float*)(smem + 2 * STAGE_B);

    const int tid  = threadIdx.x;
    const int w    = tid >> 5;
    const int lane = tid & 31;
    const int wm   = w >> 2;
    const int wn   = w & 3;
    const size_t mBase = (size_t)blockIdx.y * 128;
    const int    nBase = blockIdx.x * 128;

    if (tid < 128) bias_s[tid] = bias[nBase + tid];

    const __nv_bfloat16* A_h = Ah + mBase * DHID;
    const __nv_bfloat16* A_l = Al + mBase * DHID;
    const __nv_bfloat16* B_h = Bh + (size_t)nBase * DHID;
    const __nv_bfloat16* B_l = Bl + (size_t)nBase * DHID;

    const int j  = lane >> 3;
    const int rj = lane & 7;
    uint32_t aoff[4], boff[2];
#pragma unroll
    for (int mi = 0; mi < 4; ++mi)
        aoff[mi] = (uint32_t)((wm * 64 + mi * 16 + (j & 1) * 8 + rj) * GP_B + (j >> 1) * 16);
#pragma unroll
    for (int p = 0; p < 2; ++p)
        boff[p] = (uint32_t)((wn * 32 + p * 16 + (j >> 1) * 8 + rj) * GP_B + (j & 1) * 16);

    float acc[4][4][4];
#pragma unroll
    for (int mi = 0; mi < 4; ++mi)
#pragma unroll
        for (int ni = 0; ni < 4; ++ni)
#pragma unroll
            for (int r = 0; r < 4; ++r) acc[mi][ni][r] = 0.0f;

    load_stage(sb, 0, tid, A_h, A_l, B_h, B_l);
    CP_COMMIT();

    for (int t = 0; t < NCHUNK; ++t) {
        uint32_t st = sb + (uint32_t)(t & 1) * STAGE_B;
        if (t + 1 < NCHUNK) {
            load_stage(sb + (uint32_t)((t + 1) & 1) * STAGE_B, (t + 1) * 32, tid,
                       A_h, A_l, B_h, B_l);
            CP_COMMIT();
            CP_WAIT1();
        } else {
            CP_WAIT0();
        }
        __syncthreads();
        mma_chunk(st, aoff, boff, acc);
        __syncthreads();
    }

    // epilogue: bias + relu, split hi/lo bf16 store
    const int rGrp = lane >> 2;
    const int cGrp = (lane & 3) * 2;
#pragma unroll
    for (int mi = 0; mi < 4; ++mi) {
        size_t gr = mBase + wm * 64 + mi * 16 + rGrp;
#pragma unroll
        for (int ni = 0; ni < 4; ++ni) {
            int lc = wn * 32 + ni * 8 + cGrp;
            float b0 = bias_s[lc], b1 = bias_s[lc + 1];
            float v0 = fmaxf(acc[mi][ni][0] + b0, 0.0f);
            float v1 = fmaxf(acc[mi][ni][1] + b1, 0.0f);
            float v2 = fmaxf(acc[mi][ni][2] + b0, 0.0f);
            float v3 = fmaxf(acc[mi][ni][3] + b1, 0.0f);
            __nv_bfloat16 h0, h1, h2, h3, l0, l1, l2, l3;
            split2(v0, h0, l0); split2(v1, h1, l1);
            split2(v2, h2, l2); split2(v3, h3, l3);
            size_t o0 = gr * DHID + nBase + lc;
            size_t o1 = (gr + 8) * DHID + nBase + lc;
            *(__nv_bfloat162*)(Ch + o0) = __nv_bfloat162(h0, h1);
            *(__nv_bfloat162*)(Cl + o0) = __nv_bfloat162(l0, l1);
            *(__nv_bfloat162*)(Ch + o1) = __nv_bfloat162(h2, h3);
            *(__nv_bfloat162*)(Cl + o1) = __nv_bfloat162(l2, l3);
        }
    }
}

// ---------------- tensor-core fused attention --------------------------------
// smem layout (bytes):
#define SCP      132                         // sc pitch (floats)
#define SC_OFF   0                           // 128*528 = 67584
#define ST_OFF   67584                       // 2 stages x 40960 (phase 1)
#define AH_OFF   67584                       // alpha hi (reuses stage area)
#define AL_OFF   (67584 + 34816)             // 102400
#define AP_B     272                         // alpha pitch bytes (128 bf16 + pad)
#define QT_OFF   149504                      // 2 q-stages x 36864
#define QSTG_B   36864                       // hi 18432 + lo 18432
#define QP_B     144                         // q tile pitch bytes (64 bf16 + pad)
#define QB_OFF   223232                      // 128 floats
#define ASMEM    223744

__global__ __launch_bounds__(256)
void attn_tc_kernel(const __nv_bfloat16* __restrict__ Wph,
                    const __nv_bfloat16* __restrict__ Wpl,
                    const __nv_bfloat16* __restrict__ Wqh,
                    const __nv_bfloat16* __restrict__ Wql,
                    const __nv_bfloat16* __restrict__ Qh,
                    const __nv_bfloat16* __restrict__ Ql,
                    float* __restrict__ out) {
    extern __shared__ char smem[];
    uint32_t sb = smem_u32(smem);
    float* sc = (float*)(smem + SC_OFF);
    float* qb = (float*)(smem + QB_OFF);

    const int tid  = threadIdx.x;
    const int w    = tid >> 5;
    const int lane = tid & 31;
    const int wm   = w >> 2;
    const int wn   = w & 3;
    const int b    = blockIdx.y;
    const int pBase = blockIdx.x * 128;

    if (tid < 128) qb[tid] = g_qbias[b * NLQ + tid];

    const __nv_bfloat16* A_h = Wph + ((size_t)b * NLP + pBase) * DHID;
    const __nv_bfloat16* A_l = Wpl + ((size_t)b * NLP + pBase) * DHID;
    const __nv_bfloat16* B_h = Wqh + (size_t)b * NLQ * DHID;
    const __nv_bfloat16* B_l = Wql + (size_t)b * NLQ * DHID;
    const __nv_bfloat16* Q_h = Qh + (size_t)b * NLQ * DHID;
    const __nv_bfloat16* Q_l = Ql + (size_t)b * NLQ * DHID;

    const int j  = lane >> 3;
    const int rj = lane & 7;

    // ================= phase 1: scores = Wp @ Wq^T (split-bf16) =============
    {
        uint32_t aoff[4], boff[2];
#pragma unroll
        for (int mi = 0; mi < 4; ++mi)
            aoff[mi] = (uint32_t)((wm * 64 + mi * 16 + (j & 1) * 8 + rj) * GP_B + (j >> 1) * 16);
#pragma unroll
        for (int p = 0; p < 2; ++p)
            boff[p] = (uint32_t)((wn * 32 + p * 16 + (j >> 1) * 8 + rj) * GP_B + (j & 1) * 16);

        float acc[4][4][4];
#pragma unroll
        for (int mi = 0; mi < 4; ++mi)
#pragma unroll
            for (int ni = 0; ni < 4; ++ni)
#pragma unroll
                for (int r = 0; r < 4; ++r) acc[mi][ni][r] = 0.0f;

        load_stage(sb + ST_OFF, 0, tid, A_h, A_l, B_h, B_l);
        CP_COMMIT();
        for (int t = 0; t < NCHUNK; ++t) {
            uint32_t st = sb + ST_OFF + (uint32_t)(t & 1) * STAGE_B;
            if (t + 1 < NCHUNK) {
                load_stage(sb + ST_OFF + (uint32_t)((t + 1) & 1) * STAGE_B,
                           (t + 1) * 32, tid, A_h, A_l, B_h, B_l);
                CP_COMMIT();
                CP_WAIT1();
            } else {
                CP_WAIT0();
            }
            __syncthreads();
            mma_chunk(st, aoff, boff, acc);
            __syncthreads();
        }

        // epilogue -> sc (+ mask bias)
        const int rGrp = lane >> 2;
        const int cGrp = (lane & 3) * 2;
#pragma unroll
        for (int mi = 0; mi < 4; ++mi) {
            int pr = wm * 64 + mi * 16 + rGrp;
#pragma unroll
            for (int ni = 0; ni < 4; ++ni) {
                int q0 = wn * 32 + ni * 8 + cGrp;
                float b0 = qb[q0], b1 = qb[q0 + 1];
                sc[pr * SCP + q0]           = acc[mi][ni][0] + b0;
                sc[pr * SCP + q0 + 1]       = acc[mi][ni][1] + b1;
                sc[(pr + 8) * SCP + q0]     = acc[mi][ni][2] + b0;
                sc[(pr + 8) * SCP + q0 + 1] = acc[mi][ni][3] + b1;
            }
        }
    }
    __syncthreads();

    // prefetch first Q tile while softmax runs
    {
#pragma unroll
        for (int i = 0; i < 4; ++i) {
            int idx = tid + i * 256;
            int row = idx >> 3;
            int c   = idx & 7;
            uint32_t d = sb + QT_OFF + (uint32_t)(row * QP_B + c * 16);
            size_t so = (size_t)row * DHID + c * 8;
            cp16(d, Q_h + so);
            cp16(d + 18432, Q_l + so);
        }
        CP_COMMIT();
    }

    // ================= phase 2: softmax per p-row ============================
    if (tid < 128) {
        float* row = sc + tid * SCP;
        float mx = -INFINITY;
#pragma unroll 8
        for (int c = 0; c < 128; ++c) mx = fmaxf(mx, row[c]);
        float s = 0.0f;
#pragma unroll 8
        for (int c = 0; c < 128; ++c) {
            float e = __expf(row[c] - mx);
            row[c] = e;
            s += e;
        }
        float inv = 1.0f / s;
#pragma unroll 8
        for (int c = 0; c < 128; ++c) row[c] *= inv;
    }
    __syncthreads();

    // alpha -> bf16 hi/lo (smem), pitch AP_B
    {
        __nv_bfloat16* aH = (__nv_bfloat16*)(smem + AH_OFF);
        __nv_bfloat16* aL = (__nv_bfloat16*)(smem + AL_OFF);
        for (int i = tid; i < 128 * 32; i += 256) {
            int p  = i >> 5;
            int q4 = (i & 31) * 4;
            float4 v = *(float4*)&sc[p * SCP + q4];
            __nv_bfloat16 h0, h1, h2, h3, l0, l1, l2, l3;
            split2(v.x, h0, l0); split2(v.y, h1, l1);
            split2(v.z, h2, l2); split2(v.w, h3, l3);
            __nv_bfloat162* ph = (__nv_bfloat162*)(smem + AH_OFF + p * AP_B + q4 * 2);
            __nv_bfloat162* pl = (__nv_bfloat162*)(smem + AL_OFF + p * AP_B + q4 * 2);
            ph[0] = __nv_bfloat162(h0, h1); ph[1] = __nv_bfloat162(h2, h3);
            pl[0] = __nv_bfloat162(l0, l1); pl[1] = __nv_bfloat162(l2, l3);
        }
    }
    __syncthreads();

    // ================= phase 3: out = alpha @ question =======================
    {
        // A (alpha) ldsm offsets, pitch AP_B
        uint32_t aoff3[4];
#pragma unroll
        for (int mi = 0; mi < 4; ++mi)
            aoff3[mi] = (uint32_t)((wm * 64 + mi * 16 + (j & 1) * 8 + rj) * AP_B + (j >> 1) * 16);
        // B (question, trans) base offset, pitch QP_B
        uint32_t boffq = (uint32_t)(((j & 1) * 8 + rj) * QP_B + wn * 32 + (j >> 1) * 16);

        for (int dc = 0; dc < 12; ++dc) {
            uint32_t qs = sb + QT_OFF + (uint32_t)(dc & 1) * QSTG_B;
            if (dc + 1 < 12) {
                uint32_t nq = sb + QT_OFF + (uint32_t)((dc + 1) & 1) * QSTG_B;
                int koff = (dc + 1) * 64;
#pragma unroll
                for (int i = 0; i < 4; ++i) {
                    int idx = tid + i * 256;
                    int row = idx >> 3;
                    int c   = idx & 7;
                    uint32_t d = nq + (uint32_t)(row * QP_B + c * 16);
                    size_t so = (size_t)row * DHID + koff + c * 8;
                    cp16(d, Q_h + so);
                    cp16(d + 18432, Q_l + so);
                }
                CP_COMMIT();
                CP_WAIT1();
            } else {
                CP_WAIT0();
            }
            __syncthreads();

            float acc[4][2][4];
#pragma unroll
            for (int mi = 0; mi < 4; ++mi)
#pragma unroll
                for (int ni = 0; ni < 2; ++ni)
#pragma unroll
                    for (int r = 0; r < 4; ++r) acc[mi][ni][r] = 0.0f;

#pragma unroll
            for (int ks = 0; ks < 8; ++ks) {
                uint32_t ka = (uint32_t)ks * 32;     // alpha k-step bytes
                uint32_t kq = (uint32_t)ks * 16 * QP_B;
                uint32_t ah[4][4], al[4][4];
#pragma unroll
                for (int mi = 0; mi < 4; ++mi)
                    ldsm4(ah[mi][0], ah[mi][1], ah[mi][2], ah[mi][3],
                          sb + AH_OFF + aoff3[mi] + ka);
#pragma unroll
                for (int mi = 0; mi < 4; ++mi)
                    ldsm4(al[mi][0], al[mi][1], al[mi][2], al[mi][3],
                          sb + AL_OFF + aoff3[mi] + ka);
                uint32_t bh[2][2], bl[2][2];
                {
                    uint32_t r0, r1, r2, r3;
                    ldsm4t(r0, r1, r2, r3, qs + boffq + kq);
                    bh[0][0] = r0; bh[0][1] = r1; bh[1][0] = r2; bh[1][1] = r3;
                    ldsm4t(r0, r1, r2, r3, qs + 18432 + boffq + kq);
                    bl[0][0] = r0; bl[0][1] = r1; bl[1][0] = r2; bl[1][1] = r3;
                }
#pragma unroll
                for (int mi = 0; mi < 4; ++mi)
#pragma unroll
                    for (int ni = 0; ni < 2; ++ni) {
                        mma16816(acc[mi][ni], ah[mi][0], ah[mi][1], ah[mi][2], ah[mi][3],
                                 bh[ni][0], bh[ni][1]);
                        mma16816(acc[mi][ni], al[mi][0], al[mi][1], al[mi][2], al[mi][3],
                                 bh[ni][0], bh[ni][1]);
                        mma16816(acc[mi][ni], ah[mi][0], ah[mi][1], ah[mi][2], ah[mi][3],
                                 bl[ni][0], bl[ni][1]);
                    }
            }

            // store out tile
            const int rGrp = lane >> 2;
            const int cGrp = (lane & 3) * 2;
#pragma unroll
            for (int mi = 0; mi < 4; ++mi) {
                size_t gr = (size_t)b * NLP + pBase + wm * 64 + mi * 16 + rGrp;
#pragma unroll
                for (int ni = 0; ni < 2; ++ni) {
                    int d = dc * 64 + wn * 16 + ni * 8 + cGrp;
                    float2 v0 = {acc[mi][ni][0], acc[mi][ni][1]};
                    float2 v1 = {acc[mi][ni][2], acc[mi][ni][3]};
                    *(float2*)(out + gr * DHID + d)       = v0;
                    *(float2*)(out + (gr + 8) * DHID + d) = v1;
                }
            }
            __syncthreads();
        }
    }
}

// ---------------------------------------------------------------------------
extern "C" void kernel_launch(void* const* d_in, const int* in_sizes, int n_in,
                              void* d_out, int out_size) {
    const float* passage  = (const float*)d_in[0];
    const float* question = (const float*)d_in[2];
    const unsigned char* qmask = (const unsigned char*)d_in[3];
    const float* Ww = (const float*)d_in[4];
    const float* Wb = (const float*)d_in[5];
    float* out = (float*)d_out;

    __nv_bfloat16 *ph, *pl, *qh, *ql, *wth, *wtl, *wph, *wpl, *wqh, *wql;
    cudaGetSymbolAddress((void**)&ph,  g_Ph);
    cudaGetSymbolAddress((void**)&pl,  g_Pl);
    cudaGetSymbolAddress((void**)&qh,  g_Qh);
    cudaGetSymbolAddress((void**)&ql,  g_Ql);
    cudaGetSymbolAddress((void**)&wth, g_Wth);
    cudaGetSymbolAddress((void**)&wtl, g_Wtl);
    cudaGetSymbolAddress((void**)&wph, g_Wph);
    cudaGetSymbolAddress((void**)&wpl, g_Wpl);
    cudaGetSymbolAddress((void**)&wqh, g_Wqh);
    cudaGetSymbolAddress((void**)&wql, g_Wql);

    mask_prep_kernel<<<1, 256>>>(qmask, NB * NLQ);

    int np4 = NB * NLP * DHID / 4;
    int nq4 = NB * NLQ * DHID / 4;
    split_kernel<<<(np4 + 255) / 256, 256>>>((const float4*)passage,
                                             (__nv_bfloat162*)ph, (__nv_bfloat162*)pl, np4);
    split_kernel<<<(nq4 + 255) / 256, 256>>>((const float4*)question,
                                             (__nv_bfloat162*)qh, (__nv_bfloat162*)ql, nq4);
    wsplit_kernel<<<dim3(DHID / 32, DHID / 32), dim3(32, 8)>>>(Ww, wth, wtl);

    cudaFuncSetAttribute(gemm_mma_kernel, cudaFuncAttributeMaxDynamicSharedMemorySize, GSMEM);
    gemm_mma_kernel<<<dim3(DHID / 128, (NB * NLQ) / 128), 256, GSMEM>>>(
        qh, ql, wth, wtl, Wb, wqh, wql);
    gemm_mma_kernel<<<dim3(DHID / 128, (NB * NLP) / 128), 256, GSMEM>>>(
        ph, pl, wth, wtl, Wb, wph, wpl);

    cudaFuncSetAttribute(attn_tc_kernel, cudaFuncAttributeMaxDynamicSharedMemorySize, ASMEM);
    attn_tc_kernel<<<dim3(NLP / 128, NB), 256, ASMEM>>>(wph, wpl, wqh, wql, qh, ql, out);
}

// round 5
// speedup vs baseline: 2.2976x; 1.0439x over previous
#include <cuda_runtime.h>
#include <cuda_bf16.h>
#include <math.h>
#include <stdint.h>
#include <stddef.h>

#define DHID 768
#define NB   64
#define NLP  1024
#define NLQ  128

// ---------------- scratch (__device__ globals; allocation-free rule) --------
__device__ float g_qbias[NB * NLQ];
__device__ __align__(16) __nv_bfloat16 g_Ph[(size_t)NB * NLP * DHID];
__device__ __align__(16) __nv_bfloat16 g_Pl[(size_t)NB * NLP * DHID];
__device__ __align__(16) __nv_bfloat16 g_Qh[(size_t)NB * NLQ * DHID];
__device__ __align__(16) __nv_bfloat16 g_Ql[(size_t)NB * NLQ * DHID];
__device__ __align__(16) __nv_bfloat16 g_Wth[DHID * DHID];   // W^T hi [n][k]
__device__ __align__(16) __nv_bfloat16 g_Wtl[DHID * DHID];   // W^T lo [n][k]
__device__ __align__(16) __nv_bfloat16 g_Wph[(size_t)NB * NLP * DHID];
__device__ __align__(16) __nv_bfloat16 g_Wpl[(size_t)NB * NLP * DHID];
__device__ __align__(16) __nv_bfloat16 g_Wqh[(size_t)NB * NLQ * DHID];
__device__ __align__(16) __nv_bfloat16 g_Wql[(size_t)NB * NLQ * DHID];

// ---------------- small asm helpers ----------------------------------------
__device__ __forceinline__ uint32_t smem_u32(const void* p) {
    uint32_t a;
    asm("{ .reg .u64 t; cvta.to.shared.u64 t, %1; cvt.u32.u64 %0, t; }" : "=r"(a) : "l"(p));
    return a;
}
__device__ __forceinline__ void cp16(uint32_t dst, const void* src) {
    asm volatile("cp.async.cg.shared.global [%0], [%1], 16;" :: "r"(dst), "l"(src));
}
#define CP_COMMIT() asm volatile("cp.async.commit_group;" ::: "memory")
#define CP_WAIT1()  asm volatile("cp.async.wait_group 1;" ::: "memory")
#define CP_WAIT0()  asm volatile("cp.async.wait_group 0;" ::: "memory")

__device__ __forceinline__ void ldsm4(uint32_t& r0, uint32_t& r1, uint32_t& r2,
                                      uint32_t& r3, uint32_t a) {
    asm volatile("ldmatrix.sync.aligned.m8n8.x4.shared.b16 {%0,%1,%2,%3}, [%4];"
                 : "=r"(r0), "=r"(r1), "=r"(r2), "=r"(r3) : "r"(a));
}
__device__ __forceinline__ void ldsm4t(uint32_t& r0, uint32_t& r1, uint32_t& r2,
                                       uint32_t& r3, uint32_t a) {
    asm volatile("ldmatrix.sync.aligned.m8n8.x4.trans.shared.b16 {%0,%1,%2,%3}, [%4];"
                 : "=r"(r0), "=r"(r1), "=r"(r2), "=r"(r3) : "r"(a));
}
__device__ __forceinline__ void mma16816(float* c, uint32_t a0, uint32_t a1,
                                         uint32_t a2, uint32_t a3,
                                         uint32_t b0, uint32_t b1) {
    asm volatile("mma.sync.aligned.m16n8k16.row.col.f32.bf16.bf16.f32 "
                 "{%0,%1,%2,%3}, {%4,%5,%6,%7}, {%8,%9}, {%0,%1,%2,%3};"
                 : "+f"(c[0]), "+f"(c[1]), "+f"(c[2]), "+f"(c[3])
                 : "r"(a0), "r"(a1), "r"(a2), "r"(a3), "r"(b0), "r"(b1));
}
__device__ __forceinline__ void split2(float v, __nv_bfloat16& h, __nv_bfloat16& l) {
    h = __float2bfloat16(v);
    l = __float2bfloat16(v - __bfloat162float(h));
}

// ---------------- mask prep (dtype-sniffing) --------------------------------
__global__ void mask_prep_kernel(const unsigned char* __restrict__ qm, int n) {
    __shared__ int mode;
    if (threadIdx.x == 0) mode = 0;
    __syncthreads();
    for (int i = threadIdx.x; i < n; i += blockDim.x) {
        int r = i & 3;
        unsigned char c = qm[i];
        if (r != 0 && c != 0) {
            if (r == 3 && c == 0x3F) atomicMax(&mode, 2);
            else                     atomicMax(&mode, 1);
        }
    }
    __syncthreads();
    int m = mode;
    for (int i = threadIdx.x; i < n; i += blockDim.x) {
        int v;
        if (m == 2)      v = (((const float*)(const void*)qm)[i] != 0.0f);
        else if (m == 1) v = (qm[i] != 0);
        else             v = (((const int*)(const void*)qm)[i] != 0);
        g_qbias[i] = v ? -1e30f : 0.0f;
    }
}

// ---------------- fp32 -> (hi,lo) bf16 split --------------------------------
__global__ void split_kernel(const float4* __restrict__ x,
                             __nv_bfloat162* __restrict__ h,
                             __nv_bfloat162* __restrict__ l, int n4) {
    int i = blockIdx.x * blockDim.x + threadIdx.x;
    if (i >= n4) return;
    float4 v = x[i];
    __nv_bfloat16 h0, h1, h2, h3, l0, l1, l2, l3;
    split2(v.x, h0, l0); split2(v.y, h1, l1);
    split2(v.z, h2, l2); split2(v.w, h3, l3);
    h[i * 2]     = __nv_bfloat162(h0, h1);
    h[i * 2 + 1] = __nv_bfloat162(h2, h3);
    l[i * 2]     = __nv_bfloat162(l0, l1);
    l[i * 2 + 1] = __nv_bfloat162(l2, l3);
}

// ---------------- W[k][n] -> W^T split (hi/lo) ------------------------------
__global__ void wsplit_kernel(const float* __restrict__ W,
                              __nv_bfloat16* __restrict__ Wth,
                              __nv_bfloat16* __restrict__ Wtl) {
    __shared__ float t[32][33];
    int bx = blockIdx.x * 32;  // k
    int by = blockIdx.y * 32;  // n
    for (int yy = threadIdx.y; yy < 32; yy += 8)
        t[yy][threadIdx.x] = W[(size_t)(bx + yy) * DHID + by + threadIdx.x];
    __syncthreads();
    for (int yy = threadIdx.y; yy < 32; yy += 8) {
        float v = t[threadIdx.x][yy];
        __nv_bfloat16 h, l;
        split2(v, h, l);
        size_t o = (size_t)(by + yy) * DHID + bx + threadIdx.x;
        Wth[o] = h;
        Wtl[o] = l;
    }
}

// ---------------- common tiling constants -----------------------------------
#define GP_B      80                  // smem row pitch bytes (40 bf16)
#define ARR_B     (128 * GP_B)        // 10240 per array
#define O_AH      0
#define O_AL      (1 * ARR_B)
#define O_BH      (2 * ARR_B)
#define O_BL      (3 * ARR_B)
#define STAGE_B   (4 * ARR_B)         // 40960
#define NCHUNK    (DHID / 32)         // 24

__device__ __forceinline__ void load_stage(uint32_t dst, int kc, int tid,
                                           const __nv_bfloat16* __restrict__ A_h,
                                           const __nv_bfloat16* __restrict__ A_l,
                                           const __nv_bfloat16* __restrict__ B_h,
                                           const __nv_bfloat16* __restrict__ B_l) {
#pragma unroll
    for (int i = 0; i < 2; ++i) {
        int idx = tid + i * 256;
        int row = idx >> 2;
        int c   = idx & 3;
        uint32_t d = dst + (uint32_t)(row * GP_B + c * 16);
        size_t so = (size_t)row * DHID + kc + c * 8;
        cp16(d + O_AH, A_h + so);
        cp16(d + O_AL, A_l + so);
        cp16(d + O_BH, B_h + so);
        cp16(d + O_BL, B_l + so);
    }
}

// 3-product split-bf16 mainloop chunk (2 k16 steps), accumulate into acc[4][4][4]
__device__ __forceinline__ void mma_chunk(uint32_t st, const uint32_t* aoff,
                                          const uint32_t* boff, float acc[4][4][4]) {
#pragma unroll
    for (int ks = 0; ks < 2; ++ks) {
        uint32_t k2 = (uint32_t)ks * 32;
        uint32_t ah[4][4], al[4][4], bh[4][2], bl[4][2];
#pragma unroll
        for (int mi = 0; mi < 4; ++mi)
            ldsm4(ah[mi][0], ah[mi][1], ah[mi][2], ah[mi][3], st + O_AH + aoff[mi] + k2);
#pragma unroll
        for (int mi = 0; mi < 4; ++mi)
            ldsm4(al[mi][0], al[mi][1], al[mi][2], al[mi][3], st + O_AL + aoff[mi] + k2);
#pragma unroll
        for (int p = 0; p < 2; ++p) {
            uint32_t r0, r1, r2, r3;
            ldsm4(r0, r1, r2, r3, st + O_BH + boff[p] + k2);
            bh[p * 2][0] = r0; bh[p * 2][1] = r1;
            bh[p * 2 + 1][0] = r2; bh[p * 2 + 1][1] = r3;
            ldsm4(r0, r1, r2, r3, st + O_BL + boff[p] + k2);
            bl[p * 2][0] = r0; bl[p * 2][1] = r1;
            bl[p * 2 + 1][0] = r2; bl[p * 2 + 1][1] = r3;
        }
#pragma unroll
        for (int mi = 0; mi < 4; ++mi)
#pragma unroll
            for (int ni = 0; ni < 4; ++ni) {
                mma16816(acc[mi][ni], ah[mi][0], ah[mi][1], ah[mi][2], ah[mi][3],
                         bh[ni][0], bh[ni][1]);
                mma16816(acc[mi][ni], al[mi][0], al[mi][1], al[mi][2], al[mi][3],
                         bh[ni][0], bh[ni][1]);
                mma16816(acc[mi][ni], ah[mi][0], ah[mi][1], ah[mi][2], ah[mi][3],
                         bl[ni][0], bl[ni][1]);
            }
    }
}

// ---------------- merged projection GEMM (P + Q in one launch) ---------------
// 3-stage pipeline, 1 __syncthreads per chunk.
#define GSMEM (3 * STAGE_B + 512)
#define YP    ((NB * NLP) / 128)      // 512 P row-blocks

__global__ __launch_bounds__(256)
void gemm_mma_kernel(const __nv_bfloat16* __restrict__ Ph,
                     const __nv_bfloat16* __restrict__ Pl,
                     const __nv_bfloat16* __restrict__ Qh,
                     const __nv_bfloat16* __restrict__ Ql,
                     const __nv_bfloat16* __restrict__ Bh,
                     const __nv_bfloat16* __restrict__ Bl,
                     const float* __restrict__ bias,
                     __nv_bfloat16* __restrict__ Ph_out,
                     __nv_bfloat16* __restrict__ Pl_out,
                     __nv_bfloat16* __restrict__ Qh_out,
                     __nv_bfloat16* __restrict__ Ql_out) {
    extern __shared__ char smem[];
    uint32_t sb = smem_u32(smem);
    float* bias_s = (float*)(smem + 3 * STAGE_B);

    const int tid  = threadIdx.x;
    const int w    = tid >> 5;
    const int lane = tid & 31;
    const int wm   = w >> 2;
    const int wn   = w & 3;
    const int yb   = blockIdx.y;
    const bool isQ = (yb >= YP);
    const size_t mBase = (size_t)(isQ ? yb - YP : yb) * 128;
    const int    nBase = blockIdx.x * 128;

    if (tid < 128) bias_s[tid] = bias[nBase + tid];

    const __nv_bfloat16* A_h = (isQ ? Qh : Ph) + mBase * DHID;
    const __nv_bfloat16* A_l = (isQ ? Ql : Pl) + mBase * DHID;
    const __nv_bfloat16* B_h = Bh + (size_t)nBase * DHID;
    const __nv_bfloat16* B_l = Bl + (size_t)nBase * DHID;
    __nv_bfloat16* Ch = isQ ? Qh_out : Ph_out;
    __nv_bfloat16* Cl = isQ ? Ql_out : Pl_out;

    const int j  = lane >> 3;
    const int rj = lane & 7;
    uint32_t aoff[4], boff[2];
#pragma unroll
    for (int mi = 0; mi < 4; ++mi)
        aoff[mi] = (uint32_t)((wm * 64 + mi * 16 + (j & 1) * 8 + rj) * GP_B + (j >> 1) * 16);
#pragma unroll
    for (int p = 0; p < 2; ++p)
        boff[p] = (uint32_t)((wn * 32 + p * 16 + (j >> 1) * 8 + rj) * GP_B + (j & 1) * 16);

    float acc[4][4][4];
#pragma unroll
    for (int mi = 0; mi < 4; ++mi)
#pragma unroll
        for (int ni = 0; ni < 4; ++ni)
#pragma unroll
            for (int r = 0; r < 4; ++r) acc[mi][ni][r] = 0.0f;

    load_stage(sb + 0 * STAGE_B, 0, tid, A_h, A_l, B_h, B_l);
    CP_COMMIT();
    load_stage(sb + 1 * STAGE_B, 32, tid, A_h, A_l, B_h, B_l);
    CP_COMMIT();

    for (int t = 0; t < NCHUNK; ++t) {
        if (t + 1 < NCHUNK) CP_WAIT1(); else CP_WAIT0();
        __syncthreads();
        if (t + 2 < NCHUNK) {
            load_stage(sb + (uint32_t)((t + 2) % 3) * STAGE_B, (t + 2) * 32, tid,
                       A_h, A_l, B_h, B_l);
            CP_COMMIT();
        }
        mma_chunk(sb + (uint32_t)(t % 3) * STAGE_B, aoff, boff, acc);
    }

    // epilogue: bias + relu, split hi/lo bf16 store
    const int rGrp = lane >> 2;
    const int cGrp = (lane & 3) * 2;
#pragma unroll
    for (int mi = 0; mi < 4; ++mi) {
        size_t gr = mBase + wm * 64 + mi * 16 + rGrp;
#pragma unroll
        for (int ni = 0; ni < 4; ++ni) {
            int lc = wn * 32 + ni * 8 + cGrp;
            float b0 = bias_s[lc], b1 = bias_s[lc + 1];
            float v0 = fmaxf(acc[mi][ni][0] + b0, 0.0f);
            float v1 = fmaxf(acc[mi][ni][1] + b1, 0.0f);
            float v2 = fmaxf(acc[mi][ni][2] + b0, 0.0f);
            float v3 = fmaxf(acc[mi][ni][3] + b1, 0.0f);
            __nv_bfloat16 h0, h1, h2, h3, l0, l1, l2, l3;
            split2(v0, h0, l0); split2(v1, h1, l1);
            split2(v2, h2, l2); split2(v3, h3, l3);
            size_t o0 = gr * DHID + nBase + lc;
            size_t o1 = (gr + 8) * DHID + nBase + lc;
            *(__nv_bfloat162*)(Ch + o0) = __nv_bfloat162(h0, h1);
            *(__nv_bfloat162*)(Cl + o0) = __nv_bfloat162(l0, l1);
            *(__nv_bfloat162*)(Ch + o1) = __nv_bfloat162(h2, h3);
            *(__nv_bfloat162*)(Cl + o1) = __nv_bfloat162(l2, l3);
        }
    }
}

// ---------------- tensor-core fused attention --------------------------------
// smem layout (bytes):
#define SCP      132                         // sc pitch (floats)
#define SC_OFF   0                           // 128*528 = 67584
#define ST_OFF   67584                       // 3 stages x 40960 (phase 1)
#define AH_OFF   67584                       // alpha hi (reuses dead stage area)
#define AL_OFF   102400
#define AP_B     272                         // alpha pitch bytes (128 bf16 + pad)
#define QT_OFF   137216                      // 2 q-stages x 36864
#define QSTG_B   36864                       // hi 18432 + lo 18432
#define QP_B     144                         // q tile pitch bytes (64 bf16 + pad)
#define QB_OFF   210944                      // 128 floats
#define ASMEM    211456

__global__ __launch_bounds__(256)
void attn_tc_kernel(const __nv_bfloat16* __restrict__ Wph,
                    const __nv_bfloat16* __restrict__ Wpl,
                    const __nv_bfloat16* __restrict__ Wqh,
                    const __nv_bfloat16* __restrict__ Wql,
                    const __nv_bfloat16* __restrict__ Qh,
                    const __nv_bfloat16* __restrict__ Ql,
                    float* __restrict__ out) {
    extern __shared__ char smem[];
    uint32_t sb = smem_u32(smem);
    float* sc = (float*)(smem + SC_OFF);
    float* qb = (float*)(smem + QB_OFF);

    const int tid  = threadIdx.x;
    const int w    = tid >> 5;
    const int lane = tid & 31;
    const int wm   = w >> 2;
    const int wn   = w & 3;
    const int b    = blockIdx.y;
    const int pBase = blockIdx.x * 128;

    if (tid < 128) qb[tid] = g_qbias[b * NLQ + tid];

    const __nv_bfloat16* A_h = Wph + ((size_t)b * NLP + pBase) * DHID;
    const __nv_bfloat16* A_l = Wpl + ((size_t)b * NLP + pBase) * DHID;
    const __nv_bfloat16* B_h = Wqh + (size_t)b * NLQ * DHID;
    const __nv_bfloat16* B_l = Wql + (size_t)b * NLQ * DHID;
    const __nv_bfloat16* Q_h = Qh + (size_t)b * NLQ * DHID;
    const __nv_bfloat16* Q_l = Ql + (size_t)b * NLQ * DHID;

    const int j  = lane >> 3;
    const int rj = lane & 7;

    // ================= phase 1: scores = Wp @ Wq^T (split-bf16) =============
    {
        uint32_t aoff[4], boff[2];
#pragma unroll
        for (int mi = 0; mi < 4; ++mi)
            aoff[mi] = (uint32_t)((wm * 64 + mi * 16 + (j & 1) * 8 + rj) * GP_B + (j >> 1) * 16);
#pragma unroll
        for (int p = 0; p < 2; ++p)
            boff[p] = (uint32_t)((wn * 32 + p * 16 + (j >> 1) * 8 + rj) * GP_B + (j & 1) * 16);

        float acc[4][4][4];
#pragma unroll
        for (int mi = 0; mi < 4; ++mi)
#pragma unroll
            for (int ni = 0; ni < 4; ++ni)
#pragma unroll
                for (int r = 0; r < 4; ++r) acc[mi][ni][r] = 0.0f;

        load_stage(sb + ST_OFF + 0 * STAGE_B, 0, tid, A_h, A_l, B_h, B_l);
        CP_COMMIT();
        load_stage(sb + ST_OFF + 1 * STAGE_B, 32, tid, A_h, A_l, B_h, B_l);
        CP_COMMIT();

        for (int t = 0; t < NCHUNK; ++t) {
            if (t + 1 < NCHUNK) CP_WAIT1(); else CP_WAIT0();
            __syncthreads();
            if (t + 2 < NCHUNK) {
                load_stage(sb + ST_OFF + (uint32_t)((t + 2) % 3) * STAGE_B,
                           (t + 2) * 32, tid, A_h, A_l, B_h, B_l);
                CP_COMMIT();
            }
            mma_chunk(sb + ST_OFF + (uint32_t)(t % 3) * STAGE_B, aoff, boff, acc);
        }
        __syncthreads();   // all mma done before sc overwrite below races? (sc region distinct) keep for safety

        // epilogue -> sc (+ mask bias)
        const int rGrp = lane >> 2;
        const int cGrp = (lane & 3) * 2;
#pragma unroll
        for (int mi = 0; mi < 4; ++mi) {
            int pr = wm * 64 + mi * 16 + rGrp;
#pragma unroll
            for (int ni = 0; ni < 4; ++ni) {
                int q0 = wn * 32 + ni * 8 + cGrp;
                float b0 = qb[q0], b1 = qb[q0 + 1];
                sc[pr * SCP + q0]           = acc[mi][ni][0] + b0;
                sc[pr * SCP + q0 + 1]       = acc[mi][ni][1] + b1;
                sc[(pr + 8) * SCP + q0]     = acc[mi][ni][2] + b0;
                sc[(pr + 8) * SCP + q0 + 1] = acc[mi][ni][3] + b1;
            }
        }
    }
    __syncthreads();

    // prefetch first Q tile while softmax runs (stage region is dead now)
    {
#pragma unroll
        for (int i = 0; i < 4; ++i) {
            int idx = tid + i * 256;
            int row = idx >> 3;
            int c   = idx & 7;
            uint32_t d = sb + QT_OFF + (uint32_t)(row * QP_B + c * 16);
            size_t so = (size_t)row * DHID + c * 8;
            cp16(d, Q_h + so);
            cp16(d + 18432, Q_l + so);
        }
        CP_COMMIT();
    }

    // ================= phase 2: softmax per p-row ============================
    if (tid < 128) {
        float* row = sc + tid * SCP;
        float mx = -INFINITY;
#pragma unroll 8
        for (int c = 0; c < 128; ++c) mx = fmaxf(mx, row[c]);
        float s = 0.0f;
#pragma unroll 8
        for (int c = 0; c < 128; ++c) {
            float e = __expf(row[c] - mx);
            row[c] = e;
            s += e;
        }
        float inv = 1.0f / s;
#pragma unroll 8
        for (int c = 0; c < 128; ++c) row[c] *= inv;
    }
    __syncthreads();

    // alpha -> bf16 hi/lo (smem), pitch AP_B
    {
        for (int i = tid; i < 128 * 32; i += 256) {
            int p  = i >> 5;
            int q4 = (i & 31) * 4;
            float4 v = *(float4*)&sc[p * SCP + q4];
            __nv_bfloat16 h0, h1, h2, h3, l0, l1, l2, l3;
            split2(v.x, h0, l0); split2(v.y, h1, l1);
            split2(v.z, h2, l2); split2(v.w, h3, l3);
            __nv_bfloat162* ph = (__nv_bfloat162*)(smem + AH_OFF + p * AP_B + q4 * 2);
            __nv_bfloat162* pl = (__nv_bfloat162*)(smem + AL_OFF + p * AP_B + q4 * 2);
            ph[0] = __nv_bfloat162(h0, h1); ph[1] = __nv_bfloat162(h2, h3);
            pl[0] = __nv_bfloat162(l0, l1); pl[1] = __nv_bfloat162(l2, l3);
        }
    }
    __syncthreads();

    // ================= phase 3: out = alpha @ question =======================
    {
        uint32_t aoff3[4];
#pragma unroll
        for (int mi = 0; mi < 4; ++mi)
            aoff3[mi] = (uint32_t)((wm * 64 + mi * 16 + (j & 1) * 8 + rj) * AP_B + (j >> 1) * 16);
        uint32_t boffq = (uint32_t)(((j & 1) * 8 + rj) * QP_B + wn * 32 + (j >> 1) * 16);

        for (int dc = 0; dc < 12; ++dc) {
            uint32_t qs = sb + QT_OFF + (uint32_t)(dc & 1) * QSTG_B;
            if (dc + 1 < 12) {
                uint32_t nq = sb + QT_OFF + (uint32_t)((dc + 1) & 1) * QSTG_B;
                int koff = (dc + 1) * 64;
#pragma unroll
                for (int i = 0; i < 4; ++i) {
                    int idx = tid + i * 256;
                    int row = idx >> 3;
                    int c   = idx & 7;
                    uint32_t d = nq + (uint32_t)(row * QP_B + c * 16);
                    size_t so = (size_t)row * DHID + koff + c * 8;
                    cp16(d, Q_h + so);
                    cp16(d + 18432, Q_l + so);
                }
                CP_COMMIT();
                CP_WAIT1();
            } else {
                CP_WAIT0();
            }
            __syncthreads();

            float acc[4][2][4];
#pragma unroll
            for (int mi = 0; mi < 4; ++mi)
#pragma unroll
                for (int ni = 0; ni < 2; ++ni)
#pragma unroll
                    for (int r = 0; r < 4; ++r) acc[mi][ni][r] = 0.0f;

#pragma unroll
            for (int ks = 0; ks < 8; ++ks) {
                uint32_t ka = (uint32_t)ks * 32;
                uint32_t kq = (uint32_t)ks * 16 * QP_B;
                uint32_t ah[4][4], al[4][4];
#pragma unroll
                for (int mi = 0; mi < 4; ++mi)
                    ldsm4(ah[mi][0], ah[mi][1], ah[mi][2], ah[mi][3],
                          sb + AH_OFF + aoff3[mi] + ka);
#pragma unroll
                for (int mi = 0; mi < 4; ++mi)
                    ldsm4(al[mi][0], al[mi][1], al[mi][2], al[mi][3],
                          sb + AL_OFF + aoff3[mi] + ka);
                uint32_t bh[2][2], bl[2][2];
                {
                    uint32_t r0, r1, r2, r3;
                    ldsm4t(r0, r1, r2, r3, qs + boffq + kq);
                    bh[0][0] = r0; bh[0][1] = r1; bh[1][0] = r2; bh[1][1] = r3;
                    ldsm4t(r0, r1, r2, r3, qs + 18432 + boffq + kq);
                    bl[0][0] = r0; bl[0][1] = r1; bl[1][0] = r2; bl[1][1] = r3;
                }
#pragma unroll
                for (int mi = 0; mi < 4; ++mi)
#pragma unroll
                    for (int ni = 0; ni < 2; ++ni) {
                        mma16816(acc[mi][ni], ah[mi][0], ah[mi][1], ah[mi][2], ah[mi][3],
                                 bh[ni][0], bh[ni][1]);
                        mma16816(acc[mi][ni], al[mi][0], al[mi][1], al[mi][2], al[mi][3],
                                 bh[ni][0], bh[ni][1]);
                        mma16816(acc[mi][ni], ah[mi][0], ah[mi][1], ah[mi][2], ah[mi][3],
                                 bl[ni][0], bl[ni][1]);
                    }
            }

            const int rGrp = lane >> 2;
            const int cGrp = (lane & 3) * 2;
#pragma unroll
            for (int mi = 0; mi < 4; ++mi) {
                size_t gr = (size_t)b * NLP + pBase + wm * 64 + mi * 16 + rGrp;
#pragma unroll
                for (int ni = 0; ni < 2; ++ni) {
                    int d = dc * 64 + wn * 16 + ni * 8 + cGrp;
                    float2 v0 = {acc[mi][ni][0], acc[mi][ni][1]};
                    float2 v1 = {acc[mi][ni][2], acc[mi][ni][3]};
                    *(float2*)(out + gr * DHID + d)       = v0;
                    *(float2*)(out + (gr + 8) * DHID + d) = v1;
                }
            }
            __syncthreads();
        }
    }
}

// ---------------------------------------------------------------------------
extern "C" void kernel_launch(void* const* d_in, const int* in_sizes, int n_in,
                              void* d_out, int out_size) {
    const float* passage  = (const float*)d_in[0];
    const float* question = (const float*)d_in[2];
    const unsigned char* qmask = (const unsigned char*)d_in[3];
    const float* Ww = (const float*)d_in[4];
    const float* Wb = (const float*)d_in[5];
    float* out = (float*)d_out;

    __nv_bfloat16 *ph, *pl, *qh, *ql, *wth, *wtl, *wph, *wpl, *wqh, *wql;
    cudaGetSymbolAddress((void**)&ph,  g_Ph);
    cudaGetSymbolAddress((void**)&pl,  g_Pl);
    cudaGetSymbolAddress((void**)&qh,  g_Qh);
    cudaGetSymbolAddress((void**)&ql,  g_Ql);
    cudaGetSymbolAddress((void**)&wth, g_Wth);
    cudaGetSymbolAddress((void**)&wtl, g_Wtl);
    cudaGetSymbolAddress((void**)&wph, g_Wph);
    cudaGetSymbolAddress((void**)&wpl, g_Wpl);
    cudaGetSymbolAddress((void**)&wqh, g_Wqh);
    cudaGetSymbolAddress((void**)&wql, g_Wql);

    mask_prep_kernel<<<1, 256>>>(qmask, NB * NLQ);

    int np4 = NB * NLP * DHID / 4;
    int nq4 = NB * NLQ * DHID / 4;
    split_kernel<<<(np4 + 255) / 256, 256>>>((const float4*)passage,
                                             (__nv_bfloat162*)ph, (__nv_bfloat162*)pl, np4);
    split_kernel<<<(nq4 + 255) / 256, 256>>>((const float4*)question,
                                             (__nv_bfloat162*)qh, (__nv_bfloat162*)ql, nq4);
    wsplit_kernel<<<dim3(DHID / 32, DHID / 32), dim3(32, 8)>>>(Ww, wth, wtl);

    cudaFuncSetAttribute(gemm_mma_kernel, cudaFuncAttributeMaxDynamicSharedMemorySize, GSMEM);
    gemm_mma_kernel<<<dim3(DHID / 128, YP + (NB * NLQ) / 128), 256, GSMEM>>>(
        ph, pl, qh, ql, wth, wtl, Wb, wph, wpl, wqh, wql);

    cudaFuncSetAttribute(attn_tc_kernel, cudaFuncAttributeMaxDynamicSharedMemorySize, ASMEM);
    attn_tc_kernel<<<dim3(NLP / 128, NB), 256, ASMEM>>>(wph, wpl, wqh, wql, qh, ql, out);
}